// round 3
// baseline (speedup 1.0000x reference)
#include <cuda_runtime.h>
#include <mma.h>
#include <cstdint>

using namespace nvcuda;

static constexpr int B_    = 1024;
static constexpr int NNODE = 10;
static constexpr int FIN   = 2048;
static constexpr int FOUT  = 128;
static constexpr int NH    = 8;
static constexpr int M1    = B_ * NNODE;      // 10240 rows
static constexpr int NCAT  = 2 * FOUT * NH;   // 2048 cols of AC

// Scratch (static device arrays: allocation-free per harness rules)
__device__ float g_emb[(size_t)M1 * FOUT];          // 5.2 MB
__device__ float g_AC [(size_t)M1 * NCAT];          // 83.9 MB

// ---------------------------------------------------------------------------
// GEMM1: emb[10240,128] = X[10240,2048] @ Wp[2048,128] + bp
// Block tile 64x128, BK=32, 8 warps (warp tile 32x32), tf32 wmma m16n16k8.
// Single-stage register prefetch pipeline.
// ---------------------------------------------------------------------------
__global__ void __launch_bounds__(256) gemm1_kernel(const float* __restrict__ X,
                                                    const float* __restrict__ Wp,
                                                    const float* __restrict__ bp)
{
    __shared__ __align__(16) float sm[8192];   // 32 KB
    float* sA = sm;          // 64 x 32
    float* sB = sm + 2048;   // 32 x 128

    const int t    = threadIdx.x;
    const int m0   = blockIdx.x * 64;
    const int warp = t >> 5;
    const int wm   = warp >> 2;   // 0..1
    const int wn   = warp & 3;    // 0..3

    wmma::fragment<wmma::accumulator,16,16,8,float> acc[2][2];
    #pragma unroll
    for (int i=0;i<2;i++)
        #pragma unroll
        for (int j=0;j<2;j++) wmma::fill_fragment(acc[i][j], 0.0f);

    float4 pa[2], pb[4];
    #pragma unroll
    for (int i=0;i<2;i++){ int idx=t+i*256; int r=idx>>3, c=(idx&7)<<2;
        pa[i] = *(const float4*)(X + (size_t)(m0+r)*FIN + c); }
    #pragma unroll
    for (int i=0;i<4;i++){ int idx=t+i*256; int r=idx>>5, c=(idx&31)<<2;
        pb[i] = *(const float4*)(Wp + (size_t)r*FOUT + c); }

    for (int k0 = 0; k0 < FIN; k0 += 32)
    {
        #pragma unroll
        for (int i=0;i<2;i++){ int idx=t+i*256; int r=idx>>3, c=(idx&7)<<2;
            *(float4*)(sA + r*32 + c) = pa[i]; }
        #pragma unroll
        for (int i=0;i<4;i++){ int idx=t+i*256; int r=idx>>5, c=(idx&31)<<2;
            *(float4*)(sB + r*128 + c) = pb[i]; }
        __syncthreads();

        const int kn = k0 + 32;
        if (kn < FIN){
            #pragma unroll
            for (int i=0;i<2;i++){ int idx=t+i*256; int r=idx>>3, c=(idx&7)<<2;
                pa[i] = *(const float4*)(X + (size_t)(m0+r)*FIN + kn + c); }
            #pragma unroll
            for (int i=0;i<4;i++){ int idx=t+i*256; int r=idx>>5, c=(idx&31)<<2;
                pb[i] = *(const float4*)(Wp + (size_t)(kn+r)*FOUT + c); }
        }

        #pragma unroll
        for (int kk=0; kk<32; kk+=8){
            wmma::fragment<wmma::matrix_a,16,16,8,wmma::precision::tf32,wmma::row_major> af[2];
            wmma::fragment<wmma::matrix_b,16,16,8,wmma::precision::tf32,wmma::row_major> bf[2];
            #pragma unroll
            for (int i=0;i<2;i++){
                wmma::load_matrix_sync(af[i], sA + (wm*32 + i*16)*32 + kk, 32);
                #pragma unroll
                for (int e=0;e<af[i].num_elements;e++) af[i].x[e] = wmma::__float_to_tf32(af[i].x[e]);
            }
            #pragma unroll
            for (int j=0;j<2;j++){
                wmma::load_matrix_sync(bf[j], sB + kk*128 + wn*32 + j*16, 128);
                #pragma unroll
                for (int e=0;e<bf[j].num_elements;e++) bf[j].x[e] = wmma::__float_to_tf32(bf[j].x[e]);
            }
            #pragma unroll
            for (int i=0;i<2;i++)
                #pragma unroll
                for (int j=0;j<2;j++)
                    wmma::mma_sync(acc[i][j], af[i], bf[j], acc[i][j]);
        }
        __syncthreads();
    }

    // Epilogue: accum -> smem -> (+bias) -> global
    #pragma unroll
    for (int i=0;i<2;i++)
        #pragma unroll
        for (int j=0;j<2;j++)
            wmma::store_matrix_sync(sm + (wm*32+i*16)*128 + wn*32 + j*16, acc[i][j], 128, wmma::mem_row_major);
    __syncthreads();
    #pragma unroll
    for (int i=0;i<8;i++){
        int idx = t + i*256;          // float4 index, 0..2047
        int r = idx >> 5;             // row 0..63 (32 float4 per 128-col row)
        int c = (idx & 31) << 2;
        float4 v  = *(float4*)(sm + r*128 + c);
        float4 bb = *(const float4*)(bp + c);
        v.x += bb.x; v.y += bb.y; v.z += bb.z; v.w += bb.w;
        *(float4*)(g_emb + (size_t)(m0+r)*FOUT + c) = v;
    }
}

// ---------------------------------------------------------------------------
// GEMM2: AC[10240,2048] = emb[10240,128] @ Wcat[128,2048] (+ b1 on A-halves)
// Column tile t's B matrix is the contiguous slab W1 + t*128*128 (row-major
// 128x128, rows = k). Grid (160, 16). Same block structure as GEMM1.
// ---------------------------------------------------------------------------
__global__ void __launch_bounds__(256) gemm2_kernel(const float* __restrict__ W1,
                                                    const float* __restrict__ b1)
{
    __shared__ __align__(16) float sm[8192];
    float* sA = sm;
    float* sB = sm + 2048;

    const int t    = threadIdx.x;
    const int m0   = blockIdx.x * 64;
    const int nt   = blockIdx.y;                  // column tile 0..15
    const float* Bt = W1 + (size_t)nt * (128*128);
    const int warp = t >> 5;
    const int wm   = warp >> 2;
    const int wn   = warp & 3;

    wmma::fragment<wmma::accumulator,16,16,8,float> acc[2][2];
    #pragma unroll
    for (int i=0;i<2;i++)
        #pragma unroll
        for (int j=0;j<2;j++) wmma::fill_fragment(acc[i][j], 0.0f);

    float4 pa[2], pb[4];
    #pragma unroll
    for (int i=0;i<2;i++){ int idx=t+i*256; int r=idx>>3, c=(idx&7)<<2;
        pa[i] = *(const float4*)(g_emb + (size_t)(m0+r)*FOUT + c); }
    #pragma unroll
    for (int i=0;i<4;i++){ int idx=t+i*256; int r=idx>>5, c=(idx&31)<<2;
        pb[i] = *(const float4*)(Bt + (size_t)r*128 + c); }

    for (int k0 = 0; k0 < 128; k0 += 32)
    {
        #pragma unroll
        for (int i=0;i<2;i++){ int idx=t+i*256; int r=idx>>3, c=(idx&7)<<2;
            *(float4*)(sA + r*32 + c) = pa[i]; }
        #pragma unroll
        for (int i=0;i<4;i++){ int idx=t+i*256; int r=idx>>5, c=(idx&31)<<2;
            *(float4*)(sB + r*128 + c) = pb[i]; }
        __syncthreads();

        const int kn = k0 + 32;
        if (kn < 128){
            #pragma unroll
            for (int i=0;i<2;i++){ int idx=t+i*256; int r=idx>>3, c=(idx&7)<<2;
                pa[i] = *(const float4*)(g_emb + (size_t)(m0+r)*FOUT + kn + c); }
            #pragma unroll
            for (int i=0;i<4;i++){ int idx=t+i*256; int r=idx>>5, c=(idx&31)<<2;
                pb[i] = *(const float4*)(Bt + (size_t)(kn+r)*128 + c); }
        }

        #pragma unroll
        for (int kk=0; kk<32; kk+=8){
            wmma::fragment<wmma::matrix_a,16,16,8,wmma::precision::tf32,wmma::row_major> af[2];
            wmma::fragment<wmma::matrix_b,16,16,8,wmma::precision::tf32,wmma::row_major> bf[2];
            #pragma unroll
            for (int i=0;i<2;i++){
                wmma::load_matrix_sync(af[i], sA + (wm*32 + i*16)*32 + kk, 32);
                #pragma unroll
                for (int e=0;e<af[i].num_elements;e++) af[i].x[e] = wmma::__float_to_tf32(af[i].x[e]);
            }
            #pragma unroll
            for (int j=0;j<2;j++){
                wmma::load_matrix_sync(bf[j], sB + kk*128 + wn*32 + j*16, 128);
                #pragma unroll
                for (int e=0;e<bf[j].num_elements;e++) bf[j].x[e] = wmma::__float_to_tf32(bf[j].x[e]);
            }
            #pragma unroll
            for (int i=0;i<2;i++)
                #pragma unroll
                for (int j=0;j<2;j++)
                    wmma::mma_sync(acc[i][j], af[i], bf[j], acc[i][j]);
        }
        __syncthreads();
    }

    #pragma unroll
    for (int i=0;i<2;i++)
        #pragma unroll
        for (int j=0;j<2;j++)
            wmma::store_matrix_sync(sm + (wm*32+i*16)*128 + wn*32 + j*16, acc[i][j], 128, wmma::mem_row_major);
    __syncthreads();

    const bool isA = ((nt & 1) == 0);           // even tiles = A-half -> add b1
    const float* bias = b1 + (nt >> 1) * 128;
    #pragma unroll
    for (int i=0;i<8;i++){
        int idx = t + i*256;
        int r = idx >> 5;
        int c = (idx & 31) << 2;
        float4 v = *(float4*)(sm + r*128 + c);
        if (isA){
            float4 bb = *(const float4*)(bias + c);
            v.x += bb.x; v.y += bb.y; v.z += bb.z; v.w += bb.w;
        }
        *(float4*)(g_AC + (size_t)(m0+r)*NCAT + (size_t)nt*128 + c) = v;
    }
}

// ---------------------------------------------------------------------------
// Combine: per (b,h), S[i,k] = sum_f leakyrelu(A[i,f]+C[k,f])*W2[h,f] + b2[h]
// then the src = j + (j>=i) gather into adj[b,h,j,i]; row 9 zeroed.
// Grid (1024, 8), 128 threads (4 warps x 25 pairs).
// ---------------------------------------------------------------------------
__global__ void __launch_bounds__(128) combine_kernel(const float* __restrict__ W2,
                                                      const float* __restrict__ b2,
                                                      float* __restrict__ out)
{
    __shared__ float sA[NNODE*128];
    __shared__ float sC[NNODE*128];
    __shared__ float sW[128];

    const int b = blockIdx.x, h = blockIdx.y;
    const int t = threadIdx.x;

    const float* base = g_AC + (size_t)b * NNODE * NCAT + (size_t)h * 256;
    #pragma unroll
    for (int i=0;i<NNODE;i++){
        sA[i*128 + t] = base[(size_t)i*NCAT + t];          // A half (b1 folded in)
        sC[i*128 + t] = base[(size_t)i*NCAT + 128 + t];    // C half
    }
    sW[t] = W2[h*128 + t];
    __syncthreads();

    const float bb   = b2[h];
    const int warp   = t >> 5;
    const int lane   = t & 31;
    float* o = out + ((size_t)(b*NH + h)) * 100;

    for (int p = warp; p < 100; p += 4){
        const int i = p / 10, k = p % 10;
        float a = 0.f;
        #pragma unroll
        for (int u=0; u<4; u++){
            int f = lane + u*32;
            float v = sA[i*128+f] + sC[k*128+f];
            v = (v > 0.f) ? v : 0.2f * v;
            a += v * sW[f];
        }
        #pragma unroll
        for (int s=16; s; s>>=1) a += __shfl_xor_sync(0xffffffffu, a, s);
        if (lane == 0 && i != k){
            const int j = (k < i) ? k : (k - 1);   // inverse of src = j + (j>=i)
            o[j*10 + i] = a + bb;
        }
    }
    if (t < 10) o[90 + t] = 0.0f;   // adj row n-1..d_max-1 stays zero
}

// ---------------------------------------------------------------------------
extern "C" void kernel_launch(void* const* d_in, const int* in_sizes, int n_in,
                              void* d_out, int out_size)
{
    const float* X  = (const float*)d_in[0];   // object_features (B,10,2048,1,1)
    // d_in[1] = scene_geometry (unused by reference math)
    const float* Wp = (const float*)d_in[2];
    const float* bp = (const float*)d_in[3];
    const float* W1 = (const float*)d_in[4];
    const float* b1 = (const float*)d_in[5];
    const float* W2 = (const float*)d_in[6];
    const float* b2 = (const float*)d_in[7];
    float* out = (float*)d_out;

    gemm1_kernel<<<M1/64, 256>>>(X, Wp, bp);
    gemm2_kernel<<<dim3(M1/64, NCAT/128), 256>>>(W1, b1);
    combine_kernel<<<dim3(B_, NH), 128>>>(W2, b2, out);
    (void)in_sizes; (void)n_in; (void)out_size;
}

// round 6
// speedup vs baseline: 2.3330x; 2.3330x over previous
#include <cuda_runtime.h>
#include <cuda_fp16.h>
#include <mma.h>
#include <cstdint>

using namespace nvcuda;

static constexpr int B_    = 1024;
static constexpr int NNODE = 10;
static constexpr int FIN   = 2048;
static constexpr int FOUT  = 128;
static constexpr int NH    = 8;
static constexpr int HID   = 128;
static constexpr int M1    = B_ * NNODE;      // 10240 rows

// emb stored as f16 (fp32 accum rounded once) — 2.6 MB
__device__ __half g_emb[(size_t)M1 * FOUT];

// ---------------------------------------------------------------------------
// GEMM1: emb[10240,128] = X[10240,2048] @ Wp[2048,128] + bp   (f16 in, f32 acc)
// Block 64x128, BK=64, 8 warps (warp tile 32x32), double-buffered padded f16
// smem, 12xfloat4 register prefetch issued a full body ahead.
// Dynamic smem: sA [2][64][72] f16 (18432 B), sB [2][64][136] f16 (34816 B).
// ---------------------------------------------------------------------------
static constexpr int G1_SA_STR  = 72;
static constexpr int G1_SB_STR  = 136;
static constexpr int G1_SA_BUF  = 64 * G1_SA_STR;           // halves per buffer
static constexpr int G1_SB_BUF  = 64 * G1_SB_STR;
static constexpr int G1_SMEM    = 2*G1_SA_BUF*2 + 2*G1_SB_BUF*2;  // 53248 B

__global__ void __launch_bounds__(256) gemm1_kernel(const float* __restrict__ X,
                                                    const float* __restrict__ Wp,
                                                    const float* __restrict__ bp)
{
    extern __shared__ __align__(16) char smem_raw[];
    __half* sA = (__half*)smem_raw;                       // [2][64][72]
    __half* sB = (__half*)(smem_raw + 2*G1_SA_BUF*2);     // [2][64][136]

    const int t    = threadIdx.x;
    const int m0   = blockIdx.x * 64;
    const int warp = t >> 5;
    const int wm   = warp >> 2;      // 0..1
    const int wn   = warp & 3;       // 0..3

    wmma::fragment<wmma::accumulator,16,16,16,float> acc[2][2];
    #pragma unroll
    for (int i=0;i<2;i++)
        #pragma unroll
        for (int j=0;j<2;j++) wmma::fill_fragment(acc[i][j], 0.0f);

    float4 pa[4], pb[8];

    // A: 64x64 f32 (16 float4/row); B: 64x128 f32 (32 float4/row)
    #pragma unroll
    for (int i=0;i<4;i++){ int idx=t+i*256; int r=idx>>4, c=(idx&15)<<2;
        pa[i] = *(const float4*)(X + (size_t)(m0+r)*FIN + c); }
    #pragma unroll
    for (int i=0;i<8;i++){ int idx=t+i*256; int r=idx>>5, c=(idx&31)<<2;
        pb[i] = *(const float4*)(Wp + (size_t)r*FOUT + c); }

    // store regs -> f16 smem buffer
    auto store_tiles = [&](int buf){
        __half* a = sA + buf*G1_SA_BUF;
        __half* b = sB + buf*G1_SB_BUF;
        #pragma unroll
        for (int i=0;i<4;i++){ int idx=t+i*256; int r=idx>>4, c=(idx&15)<<2;
            __half2 h0 = __floats2half2_rn(pa[i].x, pa[i].y);
            __half2 h1 = __floats2half2_rn(pa[i].z, pa[i].w);
            __half2* p = (__half2*)(a + r*G1_SA_STR + c);
            p[0] = h0; p[1] = h1; }
        #pragma unroll
        for (int i=0;i<8;i++){ int idx=t+i*256; int r=idx>>5, c=(idx&31)<<2;
            __half2 h0 = __floats2half2_rn(pb[i].x, pb[i].y);
            __half2 h1 = __floats2half2_rn(pb[i].z, pb[i].w);
            __half2* p = (__half2*)(b + r*G1_SB_STR + c);
            p[0] = h0; p[1] = h1; }
    };

    store_tiles(0);
    __syncthreads();

    int buf = 0;
    for (int k0 = 0; k0 < FIN; k0 += 64)
    {
        const int kn = k0 + 64;
        if (kn < FIN){   // prefetch next BK into registers (full-body latency cover)
            #pragma unroll
            for (int i=0;i<4;i++){ int idx=t+i*256; int r=idx>>4, c=(idx&15)<<2;
                pa[i] = *(const float4*)(X + (size_t)(m0+r)*FIN + kn + c); }
            #pragma unroll
            for (int i=0;i<8;i++){ int idx=t+i*256; int r=idx>>5, c=(idx&31)<<2;
                pb[i] = *(const float4*)(Wp + (size_t)(kn+r)*FOUT + c); }
        }

        const __half* a = sA + buf*G1_SA_BUF;
        const __half* b = sB + buf*G1_SB_BUF;
        #pragma unroll
        for (int kk=0; kk<4; kk++){
            wmma::fragment<wmma::matrix_a,16,16,16,__half,wmma::row_major> af[2];
            wmma::fragment<wmma::matrix_b,16,16,16,__half,wmma::row_major> bf[2];
            #pragma unroll
            for (int i=0;i<2;i++)
                wmma::load_matrix_sync(af[i], a + (wm*32 + i*16)*G1_SA_STR + kk*16, G1_SA_STR);
            #pragma unroll
            for (int j=0;j<2;j++)
                wmma::load_matrix_sync(bf[j], b + (kk*16)*G1_SB_STR + wn*32 + j*16, G1_SB_STR);
            #pragma unroll
            for (int i=0;i<2;i++)
                #pragma unroll
                for (int j=0;j<2;j++)
                    wmma::mma_sync(acc[i][j], af[i], bf[j], acc[i][j]);
        }

        if (kn < FIN) store_tiles(buf ^ 1);
        __syncthreads();
        buf ^= 1;
    }

    // Epilogue: acc -> smem f32 -> (+bp) -> g_emb f16
    float* se = (float*)smem_raw;     // 64x128 f32 = 32KB (fits in 53KB)
    #pragma unroll
    for (int i=0;i<2;i++)
        #pragma unroll
        for (int j=0;j<2;j++)
            wmma::store_matrix_sync(se + (wm*32+i*16)*128 + wn*32 + j*16, acc[i][j], 128, wmma::mem_row_major);
    __syncthreads();
    #pragma unroll
    for (int i=0;i<8;i++){
        int idx = t + i*256;            // float4 index over 64x128
        int r = idx >> 5;
        int c = (idx & 31) << 2;
        float4 v  = *(float4*)(se + r*128 + c);
        float4 bb = *(const float4*)(bp + c);
        __half2 h0 = __floats2half2_rn(v.x + bb.x, v.y + bb.y);
        __half2 h1 = __floats2half2_rn(v.z + bb.z, v.w + bb.w);
        __half2* p = (__half2*)(g_emb + (size_t)(m0+r)*FOUT + c);
        p[0] = h0; p[1] = h1;
    }
}

// ---------------------------------------------------------------------------
// Fused GEMM2 + combine. Grid (128, 8), 256 threads. Block = 8 batches x 1 head.
//   A = emb @ W1[h][0:128]   (96x128, rows 80..95 padding)
//   C = emb @ W1[h][128:256]
//   S[i,k] = W2 . leakyrelu(A_i + C_k + b1) + b2 ; gather src=j+(j>=i); row 9..=0
// Dynamic smem 198144 B:
//   sEmb  f16 [96][136]   @ 0        (26112)
//   sBA   f16 [128][136]  @ 26112    (34816)
//   sBC   f16 [128][136]  @ 60928    (34816)
//   sAo   f32 [96][132]   @ 95744    (50688)
//   sCo   f32 [96][132]   @ 146432   (50688)
//   sW2   f32 [128]       @ 197120
//   sb1   f32 [128]       @ 197632
// ---------------------------------------------------------------------------
static constexpr int K2_E_STR = 136;
static constexpr int K2_B_STR = 136;
static constexpr int K2_O_STR = 132;
static constexpr int K2_SMEM  = 198144;

__global__ void __launch_bounds__(256) fused2_kernel(const float* __restrict__ W1,
                                                     const float* __restrict__ b1,
                                                     const float* __restrict__ W2,
                                                     const float* __restrict__ b2,
                                                     float* __restrict__ out)
{
    extern __shared__ __align__(16) char smem_raw[];
    __half* sEmb = (__half*)(smem_raw);
    __half* sBA  = (__half*)(smem_raw + 26112);
    __half* sBC  = (__half*)(smem_raw + 60928);
    float*  sAo  = (float*) (smem_raw + 95744);
    float*  sCo  = (float*) (smem_raw + 146432);
    float*  sW2  = (float*) (smem_raw + 197120);
    float*  sb1  = (float*) (smem_raw + 197632);

    const int t    = threadIdx.x;
    const int bg   = blockIdx.x;          // batch group (8 batches)
    const int h    = blockIdx.y;
    const int warp = t >> 5;
    const int lane = t & 31;

    // ---- loads ----
    // emb: 80 contiguous rows of g_emb starting at bg*80; 16 x uint4 per row
    // (uint4 = 16B = 8 halves, matching the 8-half column stride)
    {
        const __half* src = g_emb + (size_t)bg*80*FOUT;
        for (int i = t; i < 80*16; i += 256){
            int r = i >> 4, c8 = (i & 15) << 3;             // c8 = half offset (x8)
            uint4 v = *(const uint4*)(src + (size_t)r*FOUT + c8);
            *(uint4*)(sEmb + r*K2_E_STR + c8) = v;
        }
        // zero pad rows 80..95 (16 rows x 136 halves = 1088 u32)
        uint32_t* z = (uint32_t*)(sEmb + 80*K2_E_STR);
        for (int i = t; i < 16*K2_E_STR/2; i += 256) z[i] = 0u;
    }
    // W1 slabs: [NH][256][128]; A rows 0..127, C rows 128..255 — f32 -> f16
    {
        const float* srcA = W1 + ((size_t)h*256 + 0  )*HID;
        const float* srcB = W1 + ((size_t)h*256 + 128)*HID;
        for (int i = t; i < 4096; i += 256){                // 4096 float4 per slab
            int r = i >> 5, c = (i & 31) << 2;
            float4 va = *(const float4*)(srcA + (size_t)r*HID + c);
            float4 vc = *(const float4*)(srcB + (size_t)r*HID + c);
            __half2* pa = (__half2*)(sBA + r*K2_B_STR + c);
            pa[0] = __floats2half2_rn(va.x, va.y);
            pa[1] = __floats2half2_rn(va.z, va.w);
            __half2* pc = (__half2*)(sBC + r*K2_B_STR + c);
            pc[0] = __floats2half2_rn(vc.x, vc.y);
            pc[1] = __floats2half2_rn(vc.z, vc.w);
        }
    }
    if (t < 128){ sW2[t] = W2[h*HID + t]; sb1[t] = b1[h*HID + t]; }
    __syncthreads();

    // ---- two GEMMs: 24 tiles of 32x32 (12 for A, 12 for C), 3 per warp ----
    #pragma unroll
    for (int s = 0; s < 3; s++){
        const int ut  = warp + 8*s;           // 0..23
        const bool isC = (ut >= 12);
        const int q   = isC ? ut - 12 : ut;
        const int tr  = q >> 2;               // 0..2  (M = tr*32)
        const int tc  = q &  3;               // 0..3  (N = tc*32)
        const __half* Bs  = isC ? sBC : sBA;
        float*        Out = isC ? sCo : sAo;

        wmma::fragment<wmma::accumulator,16,16,16,float> acc[2][2];
        #pragma unroll
        for (int i=0;i<2;i++)
            #pragma unroll
            for (int j=0;j<2;j++) wmma::fill_fragment(acc[i][j], 0.0f);

        #pragma unroll
        for (int kk=0; kk<8; kk++){
            wmma::fragment<wmma::matrix_a,16,16,16,__half,wmma::row_major> af[2];
            wmma::fragment<wmma::matrix_b,16,16,16,__half,wmma::row_major> bf[2];
            #pragma unroll
            for (int i=0;i<2;i++)
                wmma::load_matrix_sync(af[i], sEmb + (tr*32 + i*16)*K2_E_STR + kk*16, K2_E_STR);
            #pragma unroll
            for (int j=0;j<2;j++)
                wmma::load_matrix_sync(bf[j], Bs + (kk*16)*K2_B_STR + tc*32 + j*16, K2_B_STR);
            #pragma unroll
            for (int i=0;i<2;i++)
                #pragma unroll
                for (int j=0;j<2;j++)
                    wmma::mma_sync(acc[i][j], af[i], bf[j], acc[i][j]);
        }
        #pragma unroll
        for (int i=0;i<2;i++)
            #pragma unroll
            for (int j=0;j<2;j++)
                wmma::store_matrix_sync(Out + (tr*32+i*16)*K2_O_STR + tc*32 + j*16,
                                        acc[i][j], K2_O_STR, wmma::mem_row_major);
    }
    __syncthreads();

    // ---- combine: 80 (b_local, i) units, 10 per warp ----
    const float b2h = b2[h];
    for (int u = warp; u < 80; u += 8){
        const int bl = u / 10, i = u % 10;
        float a[4], w[4];
        #pragma unroll
        for (int j=0;j<4;j++){
            int f = lane + 32*j;
            a[j] = sAo[u*K2_O_STR + f] + sb1[f];
            w[j] = sW2[f];
        }
        float* o = out + ((size_t)((bg*8 + bl)*NH + h)) * 100;
        #pragma unroll
        for (int k=0; k<10; k++){
            if (k == i) continue;
            const float* crow = sCo + (bl*10 + k)*K2_O_STR;
            float sum = 0.f;
            #pragma unroll
            for (int j=0;j<4;j++){
                float v = a[j] + crow[lane + 32*j];
                v = (v > 0.f) ? v : 0.2f * v;
                sum += v * w[j];
            }
            #pragma unroll
            for (int sft=16; sft; sft>>=1) sum += __shfl_xor_sync(0xffffffffu, sum, sft);
            if (lane == 0){
                const int jj = (k < i) ? k : (k - 1);   // inverse of src=j+(j>=i)
                o[jj*10 + i] = sum + b2h;
            }
        }
    }
    // zero rows 9..(d_max-1) for the 8 batches of this block
    if (t < 80){
        const int bl = t / 10, c = t % 10;
        out[((size_t)((bg*8 + bl)*NH + h)) * 100 + 90 + c] = 0.0f;
    }
}

// ---------------------------------------------------------------------------
extern "C" void kernel_launch(void* const* d_in, const int* in_sizes, int n_in,
                              void* d_out, int out_size)
{
    const float* X  = (const float*)d_in[0];
    const float* Wp = (const float*)d_in[2];
    const float* bp = (const float*)d_in[3];
    const float* W1 = (const float*)d_in[4];
    const float* b1 = (const float*)d_in[5];
    const float* W2 = (const float*)d_in[6];
    const float* b2 = (const float*)d_in[7];
    float* out = (float*)d_out;

    // Opt-in >48KB dynamic smem (idempotent; non-stream API, capture-safe)
    cudaFuncSetAttribute(gemm1_kernel,  cudaFuncAttributeMaxDynamicSharedMemorySize, G1_SMEM);
    cudaFuncSetAttribute(fused2_kernel, cudaFuncAttributeMaxDynamicSharedMemorySize, K2_SMEM);

    gemm1_kernel<<<M1/64, 256, G1_SMEM>>>(X, Wp, bp);
    fused2_kernel<<<dim3(B_/8, NH), 256, K2_SMEM>>>(W1, b1, W2, b2, out);
    (void)in_sizes; (void)n_in; (void)out_size;
}

// round 7
// speedup vs baseline: 3.7200x; 1.5945x over previous
#include <cuda_runtime.h>
#include <cuda_fp16.h>
#include <mma.h>
#include <cstdint>

using namespace nvcuda;

static constexpr int B_    = 1024;
static constexpr int NNODE = 10;
static constexpr int FIN   = 2048;
static constexpr int FOUT  = 128;
static constexpr int NH    = 8;
static constexpr int HID   = 128;
static constexpr int M1    = B_ * NNODE;      // 10240 rows

// Scratch (static device arrays: allocation-free per harness rules)
__device__ __half g_emb[(size_t)M1 * FOUT];                 // 2.6 MB
__device__ __half g_W1h[(size_t)NH * 2 * 128 * 136];        // 0.56 MB, padded stride 136

// ---------------------------------------------------------------------------
// Pack W1 (f32 [8][256][128]) -> g_W1h (f16 [8][2][128][136], cols 128..135 = 0)
// ---------------------------------------------------------------------------
__global__ void __launch_bounds__(256) w1pack_kernel(const float* __restrict__ W1)
{
    int idx = blockIdx.x * 256 + threadIdx.x;               // over 8*2*128*136
    if (idx >= NH*2*128*136) return;
    int c   = idx % 136;
    int row = idx / 136;                                    // 0..2047 = (h*2+s)*128 + r
    __half v = __float2half(0.0f);
    if (c < 128){
        // src row in W1: h*256 + s*128 + r == row's (h,s,r) flattened the same way
        v = __float2half(W1[(size_t)row * HID + c]);
    }
    g_W1h[idx] = v;
}

// ---------------------------------------------------------------------------
// GEMM1: emb[10240,128] = X[10240,2048] @ Wp[2048,128] + bp   (f16 in, f32 acc)
// Unchanged from round 6 (49us). Block 64x128, BK=64, 8 warps, double buffer.
// ---------------------------------------------------------------------------
static constexpr int G1_SA_STR  = 72;
static constexpr int G1_SB_STR  = 136;
static constexpr int G1_SA_BUF  = 64 * G1_SA_STR;
static constexpr int G1_SB_BUF  = 64 * G1_SB_STR;
static constexpr int G1_SMEM    = 2*G1_SA_BUF*2 + 2*G1_SB_BUF*2;  // 53248 B

__global__ void __launch_bounds__(256) gemm1_kernel(const float* __restrict__ X,
                                                    const float* __restrict__ Wp,
                                                    const float* __restrict__ bp)
{
    extern __shared__ __align__(16) char smem_raw[];
    __half* sA = (__half*)smem_raw;
    __half* sB = (__half*)(smem_raw + 2*G1_SA_BUF*2);

    const int t    = threadIdx.x;
    const int m0   = blockIdx.x * 64;
    const int warp = t >> 5;
    const int wm   = warp >> 2;
    const int wn   = warp & 3;

    wmma::fragment<wmma::accumulator,16,16,16,float> acc[2][2];
    #pragma unroll
    for (int i=0;i<2;i++)
        #pragma unroll
        for (int j=0;j<2;j++) wmma::fill_fragment(acc[i][j], 0.0f);

    float4 pa[4], pb[8];
    #pragma unroll
    for (int i=0;i<4;i++){ int idx=t+i*256; int r=idx>>4, c=(idx&15)<<2;
        pa[i] = *(const float4*)(X + (size_t)(m0+r)*FIN + c); }
    #pragma unroll
    for (int i=0;i<8;i++){ int idx=t+i*256; int r=idx>>5, c=(idx&31)<<2;
        pb[i] = *(const float4*)(Wp + (size_t)r*FOUT + c); }

    auto store_tiles = [&](int buf){
        __half* a = sA + buf*G1_SA_BUF;
        __half* b = sB + buf*G1_SB_BUF;
        #pragma unroll
        for (int i=0;i<4;i++){ int idx=t+i*256; int r=idx>>4, c=(idx&15)<<2;
            __half2 h0 = __floats2half2_rn(pa[i].x, pa[i].y);
            __half2 h1 = __floats2half2_rn(pa[i].z, pa[i].w);
            __half2* p = (__half2*)(a + r*G1_SA_STR + c);
            p[0] = h0; p[1] = h1; }
        #pragma unroll
        for (int i=0;i<8;i++){ int idx=t+i*256; int r=idx>>5, c=(idx&31)<<2;
            __half2 h0 = __floats2half2_rn(pb[i].x, pb[i].y);
            __half2 h1 = __floats2half2_rn(pb[i].z, pb[i].w);
            __half2* p = (__half2*)(b + r*G1_SB_STR + c);
            p[0] = h0; p[1] = h1; }
    };

    store_tiles(0);
    __syncthreads();

    int buf = 0;
    for (int k0 = 0; k0 < FIN; k0 += 64)
    {
        const int kn = k0 + 64;
        if (kn < FIN){
            #pragma unroll
            for (int i=0;i<4;i++){ int idx=t+i*256; int r=idx>>4, c=(idx&15)<<2;
                pa[i] = *(const float4*)(X + (size_t)(m0+r)*FIN + kn + c); }
            #pragma unroll
            for (int i=0;i<8;i++){ int idx=t+i*256; int r=idx>>5, c=(idx&31)<<2;
                pb[i] = *(const float4*)(Wp + (size_t)(kn+r)*FOUT + c); }
        }

        const __half* a = sA + buf*G1_SA_BUF;
        const __half* b = sB + buf*G1_SB_BUF;
        #pragma unroll
        for (int kk=0; kk<4; kk++){
            wmma::fragment<wmma::matrix_a,16,16,16,__half,wmma::row_major> af[2];
            wmma::fragment<wmma::matrix_b,16,16,16,__half,wmma::row_major> bf[2];
            #pragma unroll
            for (int i=0;i<2;i++)
                wmma::load_matrix_sync(af[i], a + (wm*32 + i*16)*G1_SA_STR + kk*16, G1_SA_STR);
            #pragma unroll
            for (int j=0;j<2;j++)
                wmma::load_matrix_sync(bf[j], b + (kk*16)*G1_SB_STR + wn*32 + j*16, G1_SB_STR);
            #pragma unroll
            for (int i=0;i<2;i++)
                #pragma unroll
                for (int j=0;j<2;j++)
                    wmma::mma_sync(acc[i][j], af[i], bf[j], acc[i][j]);
        }

        if (kn < FIN) store_tiles(buf ^ 1);
        __syncthreads();
        buf ^= 1;
    }

    float* se = (float*)smem_raw;
    #pragma unroll
    for (int i=0;i<2;i++)
        #pragma unroll
        for (int j=0;j<2;j++)
            wmma::store_matrix_sync(se + (wm*32+i*16)*128 + wn*32 + j*16, acc[i][j], 128, wmma::mem_row_major);
    __syncthreads();
    #pragma unroll
    for (int i=0;i<8;i++){
        int idx = t + i*256;
        int r = idx >> 5;
        int c = (idx & 31) << 2;
        float4 v  = *(float4*)(se + r*128 + c);
        float4 bb = *(const float4*)(bp + c);
        __half2 h0 = __floats2half2_rn(v.x + bb.x, v.y + bb.y);
        __half2 h1 = __floats2half2_rn(v.z + bb.z, v.w + bb.w);
        __half2* p = (__half2*)(g_emb + (size_t)(m0+r)*FOUT + c);
        p[0] = h0; p[1] = h1;
    }
}

// ---------------------------------------------------------------------------
// Fused GEMM2 + combine, v2. Grid (128, 8), 512 threads (16 warps).
// Block = 8 batches x 1 head.
//   A = emb @ W1h[h][0]   (96x128, rows 80..95 pad)
//   C = emb @ W1h[h][1]
//   S[i,k] = W2 . leakyrelu(A_i + b1 + C_k) + b2 ; gather src=j+(j>=i); rows 9+ = 0
// GEMM: 48 units of 16x32 tiles (3/warp). Combine: warp = (bl, i-half),
// A-rows/W2/b1 hoisted to registers, 1 LDS.128 per C-row serves 5 pairs.
// Dynamic smem 198144 B (same layout as v1).
// ---------------------------------------------------------------------------
static constexpr int K2_E_STR = 136;
static constexpr int K2_B_STR = 136;
static constexpr int K2_O_STR = 132;
static constexpr int K2_SMEM  = 198144;

__global__ void __launch_bounds__(512) fused2_kernel(const float* __restrict__ b1,
                                                     const float* __restrict__ W2,
                                                     const float* __restrict__ b2,
                                                     float* __restrict__ out)
{
    extern __shared__ __align__(16) char smem_raw[];
    __half* sEmb = (__half*)(smem_raw);
    __half* sBA  = (__half*)(smem_raw + 26112);
    __half* sBC  = (__half*)(smem_raw + 60928);
    float*  sAo  = (float*) (smem_raw + 95744);
    float*  sCo  = (float*) (smem_raw + 146432);
    float*  sW2  = (float*) (smem_raw + 197120);
    float*  sb1  = (float*) (smem_raw + 197632);

    const int t    = threadIdx.x;
    const int bg   = blockIdx.x;          // batch group (8 batches)
    const int h    = blockIdx.y;
    const int warp = t >> 5;
    const int lane = t & 31;

    // ---- stage emb (80 rows, uint4 = 8 halves) ----
    {
        const __half* src = g_emb + (size_t)bg*80*FOUT;
        for (int i = t; i < 80*16; i += 512){
            int r = i >> 4, c8 = (i & 15) << 3;
            uint4 v = *(const uint4*)(src + (size_t)r*FOUT + c8);
            *(uint4*)(sEmb + r*K2_E_STR + c8) = v;
        }
        uint32_t* z = (uint32_t*)(sEmb + 80*K2_E_STR);
        for (int i = t; i < 16*K2_E_STR/2; i += 512) z[i] = 0u;
    }
    // ---- stage W1 slabs: raw f16 copy (stride already padded to 136) ----
    {
        const uint4* srcA = (const uint4*)(g_W1h + (size_t)(h*2+0)*128*K2_B_STR);
        const uint4* srcB = (const uint4*)(g_W1h + (size_t)(h*2+1)*128*K2_B_STR);
        uint4* dA = (uint4*)sBA;
        uint4* dC = (uint4*)sBC;
        for (int i = t; i < 128*K2_B_STR/8; i += 512){   // 2176 uint4 per slab
            dA[i] = srcA[i];
            dC[i] = srcB[i];
        }
    }
    if (t < 128){ sW2[t] = W2[h*HID + t]; sb1[t] = b1[h*HID + t]; }
    __syncthreads();

    // ---- GEMM: 48 units of 16x32 (24 A + 24 C), 3 per warp ----
    #pragma unroll
    for (int s = 0; s < 3; s++){
        const int u   = warp + 16*s;          // 0..47
        const bool isC = (u >= 24);
        const int q   = isC ? u - 24 : u;
        const int tr  = q >> 2;               // 0..5  (row = tr*16)
        const int tc  = q &  3;               // 0..3  (col = tc*32)
        const __half* Bs  = isC ? sBC : sBA;
        float*        Out = isC ? sCo : sAo;

        wmma::fragment<wmma::accumulator,16,16,16,float> acc[2];
        #pragma unroll
        for (int j=0;j<2;j++) wmma::fill_fragment(acc[j], 0.0f);

        #pragma unroll
        for (int kk=0; kk<8; kk++){
            wmma::fragment<wmma::matrix_a,16,16,16,__half,wmma::row_major> af;
            wmma::fragment<wmma::matrix_b,16,16,16,__half,wmma::row_major> bf[2];
            wmma::load_matrix_sync(af, sEmb + (tr*16)*K2_E_STR + kk*16, K2_E_STR);
            #pragma unroll
            for (int j=0;j<2;j++)
                wmma::load_matrix_sync(bf[j], Bs + (kk*16)*K2_B_STR + tc*32 + j*16, K2_B_STR);
            #pragma unroll
            for (int j=0;j<2;j++)
                wmma::mma_sync(acc[j], af, bf[j], acc[j]);
        }
        #pragma unroll
        for (int j=0;j<2;j++)
            wmma::store_matrix_sync(Out + (tr*16)*K2_O_STR + tc*32 + j*16,
                                    acc[j], K2_O_STR, wmma::mem_row_major);
    }
    __syncthreads();

    // ---- combine: warp = (bl, ihalf); 5 i's x 10 k's = 50 pairs/warp ----
    // f layout: f = lane*4 + comp  (conflict-free float4 rows)
    {
        const int bl = warp >> 1;             // 0..7
        const int i0 = (warp & 1) * 5;        // 0 or 5
        const float b2h = b2[h];
        float* o = out + ((size_t)((bg*8 + bl)*NH + h)) * 100;

        float4 w4  = *(float4*)(sW2 + lane*4);
        float4 b14 = *(float4*)(sb1 + lane*4);
        float4 a4[5];
        #pragma unroll
        for (int ii=0; ii<5; ii++){
            float4 a = *(float4*)(sAo + (bl*10 + i0 + ii)*K2_O_STR + lane*4);
            a.x += b14.x; a.y += b14.y; a.z += b14.z; a.w += b14.w;
            a4[ii] = a;
        }

        #pragma unroll
        for (int k=0; k<10; k++){
            float4 c4 = *(float4*)(sCo + (bl*10 + k)*K2_O_STR + lane*4);
            #pragma unroll
            for (int ii=0; ii<5; ii++){
                float vx = a4[ii].x + c4.x;  vx = (vx > 0.f) ? vx : 0.2f*vx;
                float vy = a4[ii].y + c4.y;  vy = (vy > 0.f) ? vy : 0.2f*vy;
                float vz = a4[ii].z + c4.z;  vz = (vz > 0.f) ? vz : 0.2f*vz;
                float vw = a4[ii].w + c4.w;  vw = (vw > 0.f) ? vw : 0.2f*vw;
                float s = vx*w4.x + vy*w4.y + vz*w4.z + vw*w4.w;
                #pragma unroll
                for (int sft=16; sft; sft>>=1) s += __shfl_xor_sync(0xffffffffu, s, sft);
                const int i = i0 + ii;
                if (lane == 0 && k != i){
                    const int jj = (k < i) ? k : (k - 1);   // inverse of src=j+(j>=i)
                    o[jj*10 + i] = s + b2h;
                }
            }
        }
    }
    // zero rows 9..(d_max-1) for the 8 batches of this block
    if (t < 80){
        const int bl = t / 10, c = t % 10;
        out[((size_t)((bg*8 + bl)*NH + h)) * 100 + 90 + c] = 0.0f;
    }
}

// ---------------------------------------------------------------------------
extern "C" void kernel_launch(void* const* d_in, const int* in_sizes, int n_in,
                              void* d_out, int out_size)
{
    const float* X  = (const float*)d_in[0];
    const float* Wp = (const float*)d_in[2];
    const float* bp = (const float*)d_in[3];
    const float* W1 = (const float*)d_in[4];
    const float* b1 = (const float*)d_in[5];
    const float* W2 = (const float*)d_in[6];
    const float* b2 = (const float*)d_in[7];
    float* out = (float*)d_out;

    cudaFuncSetAttribute(gemm1_kernel,  cudaFuncAttributeMaxDynamicSharedMemorySize, G1_SMEM);
    cudaFuncSetAttribute(fused2_kernel, cudaFuncAttributeMaxDynamicSharedMemorySize, K2_SMEM);

    w1pack_kernel<<<(NH*2*128*136 + 255)/256, 256>>>(W1);
    gemm1_kernel<<<M1/64, 256, G1_SMEM>>>(X, Wp, bp);
    fused2_kernel<<<dim3(B_/8, NH), 512, K2_SMEM>>>(b1, W2, b2, out);
    (void)in_sizes; (void)n_in; (void)out_size;
}